// round 12
// baseline (speedup 1.0000x reference)
#include <cuda_runtime.h>

// Decoder_predict: batched greedy goals-NMS.  B=256, N=4096, T=30, K=6.
// scores = class * centerness, thr^2 = 4.0.
//
// V12: streaming shape that measured 2.9 TB/s (2048 CTAs) + cheap finish.
//  - 2048 CTAs (8 per batch, 512 cands each, 256 thr): stream ONLY cls+cent
//    (8 MB total). Per-warp top-6 by u32 score bits; warp 0 rank-sorts the 48
//    CTA survivors (u64 keys (score<<32)|~idx, rank = #greater — parallel
//    compares, no shuffle chains) and writes the CTA's top-6 keys to a
//    per-batch global slot array.
//  - Last CTA of each batch (atomic counter) finishes inline: read 48 keys
//    (L2), 48-thread rank-sort, parallel coord gather (one DRAM trip),
//    48-thread pairwise conflict bitmasks, then ONE thread runs the greedy
//    scan over the sorted list (exact reference semantics: descending score,
//    lowest-index tie-break, accept if no accepted point within thr).
//    Trajectories gathered by 90 threads in one parallel trip.

#define NMS_B 256
#define NMS_N 4096
#define NMS_T 30
#define NMS_K 6
#define NMS_THR2 4.0f
#define THREADS 256
#define CTAS_PER_B 8
#define CHUNK 512
#define SURV 48                  // per CTA (8 warps * 6) and per batch (8 CTAs * 6)

__device__ unsigned long long g_key[NMS_B * SURV];
__device__ unsigned int       g_cnt[NMS_B];    // monotone; checked mod 8

__global__ __launch_bounds__(THREADS)
void nms_fused_kernel(const float* __restrict__ coord,   // [B,1,N,2]
                      const float* __restrict__ cls,     // [B,1,N]
                      const float* __restrict__ traj,    // [B,1,N,T,2]
                      const float* __restrict__ cent,    // [B,1,N]
                      float* __restrict__ out)
{
    const int blk  = blockIdx.x;
    const int b    = blk >> 3;
    const int q    = blk & 7;
    const int tid  = threadIdx.x;
    const int wid  = tid >> 5;
    const int lane = tid & 31;

    __shared__ unsigned long long skey[SURV];

    // ---- Phase 1: stream scores for this 512-cand chunk; warp top-6. ----
    {
        const float2* s2 = (const float2*)(cls  + (size_t)b * NMS_N + q * CHUNK);
        const float2* e2 = (const float2*)(cent + (size_t)b * NMS_N + q * CHUNK);
        const float2 sv = s2[tid];
        const float2 ev = e2[tid];

        unsigned sc0 = __float_as_uint(sv.x * ev.x);
        unsigned sc1 = __float_as_uint(sv.y * ev.y);
        const unsigned i0 = (unsigned)(q * CHUNK + 2 * tid);

        unsigned tmax = max(sc0, sc1);
#pragma unroll
        for (int r = 0; r < NMS_K; r++) {
            unsigned m = tmax;
#pragma unroll
            for (int off = 16; off > 0; off >>= 1)
                m = max(m, __shfl_xor_sync(0xFFFFFFFFu, m, off));

            if (m == 0u) {
                // Degenerate (all remaining scores exactly 0): unique nonzero
                // sentinel, sorts last, never collides with real keys.
                if (lane == 0)
                    skey[wid * NMS_K + r] = (unsigned long long)(wid * NMS_K + r + 1);
            } else {
                const bool mine = (tmax == m);
                const unsigned bal = __ballot_sync(0xFFFFFFFFu, mine);
                const int wl = __ffs(bal) - 1;    // lowest lane = lowest idx
                if (lane == wl) {
                    const unsigned idx = (sc0 == m) ? i0 : (i0 + 1u);
                    skey[wid * NMS_K + r] =
                        ((unsigned long long)m << 32) | (unsigned)(~idx);
                    if (sc0 == m) sc0 = 0u; else sc1 = 0u;
                    tmax = max(sc0, sc1);
                }
            }
        }
    }
    __syncthreads();

    // ---- Warp 0: rank-sort the 48 survivors; write CTA top-6 to global. ----
    __shared__ unsigned s_old;
    if (wid == 0) {
        const unsigned long long k0 = skey[lane];
        const unsigned long long k1 = (lane < 16) ? skey[32 + lane] : 0ULL;
        int r0 = 0, r1 = 0;
#pragma unroll
        for (int j = 0; j < SURV; j++) {
            const unsigned long long kj = skey[j];
            r0 += (kj > k0);
            r1 += (kj > k1);
        }
        unsigned long long* dst = g_key + (size_t)b * SURV + q * NMS_K;
        if (r0 < NMS_K) dst[r0] = k0;                  // exactly 6 writes total
        if (lane < 16 && r1 < NMS_K) dst[r1] = k1;
        __syncwarp();
        __threadfence();                               // release before atomic
        if (lane == 0) s_old = atomicAdd(&g_cnt[b], 1u);
    }
    __syncthreads();
    if ((s_old & 7u) != 7u) return;                    // not the last chunk

    __threadfence();                                   // acquire side

    // ---- Finisher: exact greedy NMS over the batch's 48 survivors. ----
    __shared__ unsigned long long fk[SURV];
    __shared__ float    ssx[SURV], ssy[SURV];
    __shared__ unsigned ssc[SURV];
    __shared__ int      ssi[SURV];
    __shared__ unsigned long long cm[SURV];
    __shared__ int      sel_pos[NMS_K];

    if (tid < SURV) fk[tid] = __ldcg(&g_key[(size_t)b * SURV + tid]);
    __syncthreads();

    if (tid < SURV) {      // rank-sort + parallel coord gather (one DRAM trip)
        const unsigned long long mine = fk[tid];
        int r = 0;
#pragma unroll
        for (int j = 0; j < SURV; j++) r += (fk[j] > mine);
        const int idx = (int)(~(unsigned)mine) & (NMS_N - 1);   // safe recover
        const float2 c = ((const float2*)(coord + (size_t)b * NMS_N * 2))[idx];
        ssx[r] = c.x;  ssy[r] = c.y;
        ssc[r] = (unsigned)(mine >> 32);
        ssi[r] = idx;
    }
    __syncthreads();

    if (tid < SURV) {      // pairwise conflict bitmasks (parallel)
        const float x = ssx[tid], y = ssy[tid];
        unsigned long long mask = 0ULL;
#pragma unroll
        for (int j = 0; j < SURV; j++) {
            const float dx = ssx[j] - x;
            const float dy = ssy[j] - y;
            if (dx * dx + dy * dy < NMS_THR2) mask |= (1ULL << j);
        }
        cm[tid] = mask;
    }
    __syncthreads();

    if (tid == 0) {        // single-thread greedy scan over sorted list
        unsigned long long acc = 0ULL;
        int cnt = 0;
        for (int j = 0; j < SURV && cnt < NMS_K; j++) {
            if (!(cm[j] & acc)) { sel_pos[cnt++] = j; acc |= (1ULL << j); }
        }
        for (; cnt < NMS_K; cnt++) sel_pos[cnt] = -1;  // fallback slots
    }
    __syncthreads();

    // ---- Outputs. Layout: pred_trajs [B,K,T,2] | probs [B,K] | goals [B,K,2]
    float* out_prob = out + (size_t)NMS_B * NMS_K * NMS_T * 2;
    float* out_goal = out_prob + (size_t)NMS_B * NMS_K;

    if (tid < NMS_K) {
        const int  p     = sel_pos[tid];
        const bool valid = (p >= 0);
        // Fallback: reference keeps sel_idx = 0 -> sorted[0]'s score/traj,
        // goal stays (0,0).  sel_pos[0] is always 0 (greedy accepts first).
        out_prob[(size_t)b * NMS_K + tid] = __uint_as_float(valid ? ssc[p] : ssc[0]);
        out_goal[((size_t)b * NMS_K + tid) * 2 + 0] = valid ? ssx[p] : 0.0f;
        out_goal[((size_t)b * NMS_K + tid) * 2 + 1] = valid ? ssy[p] : 0.0f;
    }

    if (tid < NMS_K * 15) {    // 90 float4 = all 6 traj rows in one trip
        const int k  = tid / 15;
        const int qq = tid % 15;
        const int p  = sel_pos[k];
        const int src = (p >= 0) ? ssi[p] : ssi[0];
        ((float4*)out)[((size_t)b * NMS_K + k) * 15 + qq] =
            ((const float4*)traj)[((size_t)b * NMS_N + src) * 15 + qq];
    }
}

extern "C" void kernel_launch(void* const* d_in, const int* in_sizes, int n_in,
                              void* d_out, int out_size) {
    const float* coord = (const float*)d_in[0];  // outputs_coord     [B,1,N,2]
    const float* cls   = (const float*)d_in[1];  // outputs_class     [B,1,N]
    const float* traj  = (const float*)d_in[2];  // outputs_traj      [B,1,N,T,2]
    const float* cent  = (const float*)d_in[3];  // outputs_centerness[B,1,N]
    float* out = (float*)d_out;

    nms_fused_kernel<<<NMS_B * CTAS_PER_B, THREADS>>>(coord, cls, traj, cent, out);
}

// round 13
// speedup vs baseline: 1.3739x; 1.3739x over previous
#include <cuda_runtime.h>

// Decoder_predict: batched greedy goals-NMS.  B=256, N=4096, T=30, K=6.
// scores = class * centerness, thr^2 = 4.0.
//
// V13: two-kernel split (the 2048-CTA streaming shape of V3-A measured
// 2.85 TB/s; inter-kernel gap measured ~0) with a byte-dieted kernel A and a
// cheap rank/bitmask finisher as kernel B.
//  Kernel A (1024 CTAs x 256 thr; 1024 cands/CTA): stream ONLY cls+cent
//    (8.4 MB) as 2x float4/thread; per-warp top-6 by u32 score bits with
//    exact lowest-index tie-break; warp 0 rank-sorts the 48 CTA survivors
//    (count-of-greater over u64 keys, no shuffle chains) and writes the CTA
//    top-6 keys -> 24 keys per batch in global scratch.
//  Kernel B (256 CTAs x 128 thr, one wave): load 24 keys (L2), parallel
//    rank-sort, ONE parallel coord-gather DRAM trip, parallel 24x24 conflict
//    bitmask (u32), single-thread greedy scan (exact reference semantics:
//    descending score, lowest-index ties, accept if no accepted point within
//    thr; fallback slots keep idx=0 semantics), parallel traj gather.

#define NMS_B 256
#define NMS_N 4096
#define NMS_T 30
#define NMS_K 6
#define NMS_THR2 4.0f
#define A_THREADS 256
#define CTAS_PER_B 4
#define CHUNK 1024
#define CTA_SURV 48              // 8 warps * 6
#define B_SURV (CTAS_PER_B * NMS_K)   // 24 keys per batch

__device__ unsigned long long g_key[NMS_B * B_SURV];

// ---------------- Kernel A: stream scores, CTA top-6 ----------------
__global__ __launch_bounds__(A_THREADS)
void score_topk_kernel(const float* __restrict__ cls,    // [B,1,N]
                       const float* __restrict__ cent)   // [B,1,N]
{
    const int blk  = blockIdx.x;
    const int b    = blk >> 2;
    const int q    = blk & 3;
    const int tid  = threadIdx.x;
    const int wid  = tid >> 5;
    const int lane = tid & 31;

    __shared__ unsigned long long skey[CTA_SURV];

    {
        const float4* s4 = (const float4*)(cls  + (size_t)b * NMS_N + q * CHUNK);
        const float4* e4 = (const float4*)(cent + (size_t)b * NMS_N + q * CHUNK);
        const float4 sv = s4[tid];
        const float4 ev = e4[tid];

        unsigned sc[4];
        sc[0] = __float_as_uint(sv.x * ev.x);
        sc[1] = __float_as_uint(sv.y * ev.y);
        sc[2] = __float_as_uint(sv.z * ev.z);
        sc[3] = __float_as_uint(sv.w * ev.w);
        const unsigned i0 = (unsigned)(q * CHUNK + 4 * tid);

        unsigned tmax = max(max(sc[0], sc[1]), max(sc[2], sc[3]));

#pragma unroll
        for (int r = 0; r < NMS_K; r++) {
            unsigned m = tmax;
#pragma unroll
            for (int off = 16; off > 0; off >>= 1)
                m = max(m, __shfl_xor_sync(0xFFFFFFFFu, m, off));

            if (m == 0u) {
                // Degenerate (scores exhausted): unique tiny sentinel, sorts
                // last, never collides with real keys.
                if (lane == 0)
                    skey[wid * NMS_K + r] =
                        (unsigned long long)(wid * NMS_K + r + 1);
            } else {
                const bool mine = (tmax == m);
                const unsigned bal = __ballot_sync(0xFFFFFFFFu, mine);
                const int wl = __ffs(bal) - 1;    // lowest lane = lowest idx
                if (lane == wl) {
                    int jm = 3;
#pragma unroll
                    for (int j = 3; j >= 0; j--)
                        if (sc[j] == m) jm = j;   // lowest slot = lowest idx
                    skey[wid * NMS_K + r] =
                        ((unsigned long long)m << 32) | (unsigned)(~(i0 + jm));
#pragma unroll
                    for (int j = 0; j < 4; j++) if (j == jm) sc[j] = 0u;
                    tmax = max(max(sc[0], sc[1]), max(sc[2], sc[3]));
                }
            }
        }
    }
    __syncthreads();

    // Warp 0: rank the 48 survivors (count-of-greater), write CTA top-6.
    if (wid == 0) {
        const unsigned long long k0 = skey[lane];
        const unsigned long long k1 = (lane < 16) ? skey[32 + lane] : 0ULL;
        int r0 = 0, r1 = 0;
#pragma unroll
        for (int j = 0; j < CTA_SURV; j++) {
            const unsigned long long kj = skey[j];
            r0 += (kj > k0);
            r1 += (kj > k1);
        }
        unsigned long long* dst = g_key + (size_t)b * B_SURV + q * NMS_K;
        if (r0 < NMS_K) dst[r0] = k0;
        if (lane < 16 && r1 < NMS_K) dst[r1] = k1;
    }
}

// ---------------- Kernel B: rank + bitmask greedy NMS + gather ----------------
__global__ __launch_bounds__(128)
void nms_finish_kernel(const float* __restrict__ coord,  // [B,1,N,2]
                       const float* __restrict__ traj,   // [B,1,N,T,2]
                       float* __restrict__ out)
{
    const int b   = blockIdx.x;
    const int tid = threadIdx.x;

    __shared__ unsigned long long fk[B_SURV];
    __shared__ float    ssx[B_SURV], ssy[B_SURV];
    __shared__ unsigned ssc[B_SURV];
    __shared__ int      ssi[B_SURV];
    __shared__ unsigned cm[B_SURV];
    __shared__ int      sel_pos[NMS_K];

    if (tid < B_SURV) fk[tid] = g_key[(size_t)b * B_SURV + tid];
    __syncthreads();

    if (tid < B_SURV) {   // rank-sort + parallel coord gather (one DRAM trip)
        const unsigned long long mine = fk[tid];
        int r = 0;
#pragma unroll
        for (int j = 0; j < B_SURV; j++) r += (fk[j] > mine);
        const int idx = (int)(~(unsigned)mine) & (NMS_N - 1);   // safe recover
        const float2 c = ((const float2*)(coord + (size_t)b * NMS_N * 2))[idx];
        ssx[r] = c.x;  ssy[r] = c.y;
        ssc[r] = (unsigned)(mine >> 32);
        ssi[r] = idx;
    }
    __syncthreads();

    if (tid < B_SURV) {   // pairwise conflict bitmask (parallel)
        const float x = ssx[tid], y = ssy[tid];
        unsigned mask = 0u;
#pragma unroll
        for (int j = 0; j < B_SURV; j++) {
            const float dx = ssx[j] - x;
            const float dy = ssy[j] - y;
            if (dx * dx + dy * dy < NMS_THR2) mask |= (1u << j);
        }
        cm[tid] = mask;
    }
    __syncthreads();

    if (tid == 0) {       // single-thread greedy scan (exact semantics)
        unsigned acc = 0u;
        int cnt = 0;
        for (int j = 0; j < B_SURV && cnt < NMS_K; j++) {
            if (!(cm[j] & acc)) { sel_pos[cnt++] = j; acc |= (1u << j); }
        }
        for (; cnt < NMS_K; cnt++) sel_pos[cnt] = -1;   // fallback slots
    }
    __syncthreads();

    // Outputs. Layout: pred_trajs [B,K,T,2] | probs [B,K] | goals [B,K,2]
    float* out_prob = out + (size_t)NMS_B * NMS_K * NMS_T * 2;
    float* out_goal = out_prob + (size_t)NMS_B * NMS_K;

    if (tid < NMS_K) {
        const int  p     = sel_pos[tid];
        const bool valid = (p >= 0);
        // Fallback: reference keeps sel_idx = 0 -> sorted[0]'s score/traj,
        // goal (0,0).  sel_pos[0] is always 0 (greedy accepts the first).
        out_prob[(size_t)b * NMS_K + tid] =
            __uint_as_float(valid ? ssc[p] : ssc[0]);
        out_goal[((size_t)b * NMS_K + tid) * 2 + 0] = valid ? ssx[p] : 0.0f;
        out_goal[((size_t)b * NMS_K + tid) * 2 + 1] = valid ? ssy[p] : 0.0f;
    }

    if (tid < NMS_K * 15) {   // 90 float4 = all 6 traj rows, one parallel trip
        const int k = tid / 15;
        const int w = tid % 15;
        const int p = sel_pos[k];
        const int src = (p >= 0) ? ssi[p] : ssi[0];
        ((float4*)out)[((size_t)b * NMS_K + k) * 15 + w] =
            ((const float4*)traj)[((size_t)b * NMS_N + src) * 15 + w];
    }
}

extern "C" void kernel_launch(void* const* d_in, const int* in_sizes, int n_in,
                              void* d_out, int out_size) {
    const float* coord = (const float*)d_in[0];  // outputs_coord     [B,1,N,2]
    const float* cls   = (const float*)d_in[1];  // outputs_class     [B,1,N]
    const float* traj  = (const float*)d_in[2];  // outputs_traj      [B,1,N,T,2]
    const float* cent  = (const float*)d_in[3];  // outputs_centerness[B,1,N]
    float* out = (float*)d_out;

    score_topk_kernel<<<NMS_B * CTAS_PER_B, A_THREADS>>>(cls, cent);
    nms_finish_kernel<<<NMS_B, 128>>>(coord, traj, out);
}